// round 4
// baseline (speedup 1.0000x reference)
#include <cuda_runtime.h>

#define BATCH 32
#define NPTS  16384
#define GRP   128
#define KNN   64
#define HID   128
#define DIM   384

// Scratch (no allocations allowed)
__device__ float g_cent[BATCH * GRP * 3];
__device__ float g_hbar[BATCH * GRP * HID];

// ---------------------------------------------------------------------------
// Kernel 1: Farthest point sampling. One block per batch, 512 threads.
// Points live in registers (32/thread), running min-distance lives in SMEM
// (thread-private slots, strided layout -> conflict-free).
// Matches reference: idx[0]=0, emit current farthest BEFORE distance update,
// argmax picks lowest index on exact ties.
// ---------------------------------------------------------------------------
__global__ __launch_bounds__(512) void fps_kernel(const float* __restrict__ pts,
                                                  float* __restrict__ out_cent) {
    extern __shared__ unsigned char dyn_smem[];
    float* sdist = reinterpret_cast<float*>(dyn_smem);  // NPTS floats
    __shared__ float scx, scy, scz;
    __shared__ int snext;
    __shared__ float swv[16];
    __shared__ int swi[16];

    const int b = blockIdx.x;
    const float* P = pts + (size_t)b * NPTS * 3;
    const int t = threadIdx.x;

    float px[32], py[32], pz[32];
#pragma unroll
    for (int j = 0; j < 32; j++) {
        int idx = t + j * 512;
        px[j] = P[idx * 3 + 0];
        py[j] = P[idx * 3 + 1];
        pz[j] = P[idx * 3 + 2];
        sdist[idx] = 3.4e38f;
    }
    __syncthreads();

    int cur = 0;
    for (int g = 0; g < GRP; g++) {
        // broadcast coords of current farthest point
        if (t == (cur & 511)) {
            int j = cur >> 9;
            scx = px[j]; scy = py[j]; scz = pz[j];
        }
        __syncthreads();
        float cx = scx, cy = scy, cz = scz;

        if (t == 0) {
            size_t o = ((size_t)b * GRP + g) * 3;
            g_cent[o + 0] = cx; g_cent[o + 1] = cy; g_cent[o + 2] = cz;
            if (out_cent) {
                out_cent[o + 0] = cx; out_cent[o + 1] = cy; out_cent[o + 2] = cz;
            }
        }

        float bv = -1.0f;
        int bi = 0x7fffffff;
#pragma unroll
        for (int j = 0; j < 32; j++) {
            int idx = t + j * 512;
            float dx = px[j] - cx;
            float dy = py[j] - cy;
            float dz = pz[j] - cz;
            float d = dx * dx + dy * dy + dz * dz;
            float nd = fminf(sdist[idx], d);
            sdist[idx] = nd;
            if (nd > bv) { bv = nd; bi = idx; }  // idx ascending within thread
        }
        // warp argmax (tie -> lower index)
#pragma unroll
        for (int off = 16; off; off >>= 1) {
            float ov = __shfl_down_sync(0xffffffffu, bv, off);
            int oi = __shfl_down_sync(0xffffffffu, bi, off);
            if (ov > bv || (ov == bv && oi < bi)) { bv = ov; bi = oi; }
        }
        if ((t & 31) == 0) { swv[t >> 5] = bv; swi[t >> 5] = bi; }
        __syncthreads();
        if (t < 16) {
            bv = swv[t]; bi = swi[t];
#pragma unroll
            for (int off = 8; off; off >>= 1) {
                float ov = __shfl_down_sync(0x0000ffffu, bv, off);
                int oi = __shfl_down_sync(0x0000ffffu, bi, off);
                if (ov > bv || (ov == bv && oi < bi)) { bv = ov; bi = oi; }
            }
            if (t == 0) snext = bi;
        }
        __syncthreads();
        cur = snext;
    }
}

// ---------------------------------------------------------------------------
// Kernel 2: per-(b,g) exact top-64 smallest dist2 (radix select, matching
// lax.top_k stable tie semantics), then fused gelu-MLP first layer and mean
// over the 64 neighbors -> g_hbar[b*GRP+g][128].
// ---------------------------------------------------------------------------
__global__ __launch_bounds__(256) void group_kernel(const float* __restrict__ pts,
                                                    const float* __restrict__ w1,
                                                    const float* __restrict__ b1) {
    extern __shared__ unsigned char dyn_smem[];
    unsigned* s_keys = reinterpret_cast<unsigned*>(dyn_smem);  // NPTS keys

    __shared__ unsigned hist[256];
    __shared__ unsigned s_prefix;
    __shared__ int s_k;
    __shared__ int sel[KNN];
    __shared__ int eql[KNN];
    __shared__ int s_nless, s_neq;
    __shared__ float loc[KNN][3];
    __shared__ float hpart[256];

    const int g = blockIdx.x;
    const int b = blockIdx.y;
    const int t = threadIdx.x;

    const float* P = pts + (size_t)b * NPTS * 3;
    const float* C = g_cent + ((size_t)b * GRP + g) * 3;
    const float cx = C[0], cy = C[1], cz = C[2];
    const float c2 = cx * cx + cy * cy + cz * cz;

    // distances -> orderable uint keys in SMEM (reference formula)
    for (int i = t; i < NPTS; i += 256) {
        float x = P[i * 3 + 0], y = P[i * 3 + 1], z = P[i * 3 + 2];
        float p2 = x * x + y * y + z * z;
        float dot = cx * x + cy * y + cz * z;
        float f = (c2 + p2) - 2.0f * dot;
        unsigned u = __float_as_uint(f);
        u = (u & 0x80000000u) ? ~u : (u | 0x80000000u);
        s_keys[i] = u;
    }

    // 4-round MSB radix select: exact key of the 64th smallest
    unsigned prefix = 0;
    int k = KNN;
    for (int shift = 24; shift >= 0; shift -= 8) {
        hist[t & 255] = 0;  // 256 threads -> each zeros one bin
        __syncthreads();
        unsigned hmask = (shift == 24) ? 0u : (0xFFFFFFFFu << (shift + 8));
        for (int i = t; i < NPTS; i += 256) {
            unsigned key = s_keys[i];
            if ((key & hmask) == prefix)
                atomicAdd(&hist[(key >> shift) & 255u], 1u);
        }
        __syncthreads();
        if (t == 0) {
            unsigned cum = 0;
            for (int bin = 0; bin < 256; bin++) {
                unsigned c = hist[bin];
                if (cum + c >= (unsigned)k) {
                    s_k = k - (int)cum;
                    s_prefix = prefix | ((unsigned)bin << shift);
                    break;
                }
                cum += c;
            }
        }
        __syncthreads();
        prefix = s_prefix;
        k = s_k;
        __syncthreads();
    }
    const unsigned T = prefix;

    // gather: all keys < T, then fill with lowest-index ties == T
    if (t == 0) { s_nless = 0; s_neq = 0; }
    __syncthreads();
    for (int i = t; i < NPTS; i += 256) {
        unsigned key = s_keys[i];
        if (key < T) {
            int p = atomicAdd(&s_nless, 1);
            sel[p] = i;
        } else if (key == T) {
            int e = atomicAdd(&s_neq, 1);
            if (e < KNN) eql[e] = i;
        }
    }
    __syncthreads();
    if (t == 0) {
        int nless = s_nless;
        int need = KNN - nless;
        int m = (s_neq < KNN) ? s_neq : KNN;
        for (int a = 1; a < m; a++) {  // insertion sort (tiny)
            int v = eql[a];
            int c = a - 1;
            while (c >= 0 && eql[c] > v) { eql[c + 1] = eql[c]; c--; }
            eql[c + 1] = v;
        }
        for (int a = 0; a < need; a++) sel[nless + a] = eql[a];
    }
    __syncthreads();

    // local coords of selected neighbors
    if (t < KNN) {
        int idx = sel[t];
        loc[t][0] = P[idx * 3 + 0] - cx;
        loc[t][1] = P[idx * 3 + 1] - cy;
        loc[t][2] = P[idx * 3 + 2] - cz;
    }
    __syncthreads();

    // hbar[j] = mean_k gelu(loc_k . w1[:,j] + b1[j]); exact-erf gelu.
    // 256 threads: (j = t&127) x (half of k).
    const int j = t & 127;
    const float wx = w1[j], wy = w1[HID + j], wz = w1[2 * HID + j], bb = b1[j];
    float acc = 0.0f;
    const int k0 = (t >> 7) * 32;
#pragma unroll
    for (int kk = 0; kk < 32; kk++) {
        int kp = k0 + kk;
        float v = loc[kp][0] * wx + loc[kp][1] * wy + loc[kp][2] * wz + bb;
        float h = 0.5f * v * (1.0f + erff(v * 0.7071067811865476f));
        acc += h;
    }
    hpart[t] = acc;
    __syncthreads();
    if (t < HID)
        g_hbar[((size_t)b * GRP + g) * HID + t] =
            (hpart[t] + hpart[t + 128]) * (1.0f / (float)KNN);
}

// ---------------------------------------------------------------------------
// Kernel 3: tokens = hbar @ w2 + b2 (4096x384x128 GEMM), then LayerNorm.
// 16 rows per block, 384 threads (one output column each).
// ---------------------------------------------------------------------------
__global__ __launch_bounds__(384) void head_kernel(const float* __restrict__ w2,
                                                   const float* __restrict__ b2,
                                                   const float* __restrict__ gamma,
                                                   const float* __restrict__ beta,
                                                   float* __restrict__ out_tok) {
    __shared__ float sh[16 * HID];
    __shared__ float tok[16][DIM];

    const int row0 = blockIdx.x * 16;
    const int t = threadIdx.x;

    for (int i = t; i < 16 * HID; i += 384)
        sh[i] = g_hbar[(size_t)row0 * HID + i];
    __syncthreads();

    float acc[16];
#pragma unroll
    for (int r = 0; r < 16; r++) acc[r] = 0.0f;

    for (int jj = 0; jj < HID; jj++) {
        float w = w2[jj * DIM + t];
#pragma unroll
        for (int r = 0; r < 16; r++) acc[r] += sh[r * HID + jj] * w;
    }
    const float bd = b2[t];
#pragma unroll
    for (int r = 0; r < 16; r++) tok[r][t] = acc[r] + bd;
    __syncthreads();

    // LayerNorm per row: 12 warps cover 16 rows
    const int w = t >> 5, lane = t & 31;
    for (int r = w; r < 16; r += 12) {
        float s = 0.0f;
        for (int c = lane; c < DIM; c += 32) s += tok[r][c];
#pragma unroll
        for (int off = 16; off; off >>= 1) s += __shfl_xor_sync(0xffffffffu, s, off);
        float mu = s * (1.0f / DIM);
        float v = 0.0f;
        for (int c = lane; c < DIM; c += 32) {
            float d0 = tok[r][c] - mu;
            v += d0 * d0;
        }
#pragma unroll
        for (int off = 16; off; off >>= 1) v += __shfl_xor_sync(0xffffffffu, v, off);
        float rstd = rsqrtf(v * (1.0f / DIM) + 1e-5f);
        for (int c = lane; c < DIM; c += 32)
            out_tok[((size_t)row0 + r) * DIM + c] =
                (tok[r][c] - mu) * rstd * gamma[c] + beta[c];
    }
}

// ---------------------------------------------------------------------------
extern "C" void kernel_launch(void* const* d_in, const int* in_sizes, int n_in,
                              void* d_out, int out_size) {
    const float* pts   = (const float*)d_in[0];  // [32,16384,3]
    const float* w1    = (const float*)d_in[1];  // [3,128]
    const float* b1    = (const float*)d_in[2];  // [128]
    const float* w2    = (const float*)d_in[3];  // [128,384]
    const float* b2    = (const float*)d_in[4];  // [384]
    const float* gamma = (const float*)d_in[5];  // [384]
    const float* beta  = (const float*)d_in[6];  // [384]

    float* out = (float*)d_out;
    float* out_cent = nullptr;
    float* out_tok = out;
    // Expected layout: centroids [32,128,3] then tokens_ln [32,128,384]
    if (out_size == BATCH * GRP * (3 + DIM)) {
        out_cent = out;
        out_tok = out + BATCH * GRP * 3;
    }

    cudaFuncSetAttribute(fps_kernel, cudaFuncAttributeMaxDynamicSharedMemorySize,
                         NPTS * (int)sizeof(float));
    cudaFuncSetAttribute(group_kernel, cudaFuncAttributeMaxDynamicSharedMemorySize,
                         NPTS * (int)sizeof(unsigned));

    fps_kernel<<<BATCH, 512, NPTS * sizeof(float)>>>(pts, out_cent);
    group_kernel<<<dim3(GRP, BATCH), 256, NPTS * sizeof(unsigned)>>>(pts, w1, b1);
    head_kernel<<<(BATCH * GRP) / 16, 384>>>(w2, b2, gamma, beta, out_tok);
}

// round 5
// speedup vs baseline: 1.0017x; 1.0017x over previous
#include <cuda_runtime.h>

#define BATCH 32
#define NPTS  16384
#define GRP   128
#define KNN   64
#define HID   128
#define DIM   384

// Scratch (no allocations allowed)
__device__ float g_cent[BATCH * GRP * 3];
__device__ float g_hbar[BATCH * GRP * HID];

// ---------------------------------------------------------------------------
// Kernel 1: Farthest point sampling. One block per batch, 512 threads.
// Points live in registers (32/thread), running min-distance lives in SMEM
// (thread-private slots, strided layout -> conflict-free).
// Matches reference: idx[0]=0, emit current farthest BEFORE distance update,
// argmax picks lowest index on exact ties.
// ---------------------------------------------------------------------------
__global__ __launch_bounds__(512) void fps_kernel(const float* __restrict__ pts,
                                                  float* __restrict__ out_cent) {
    extern __shared__ unsigned char dyn_smem[];
    float* sdist = reinterpret_cast<float*>(dyn_smem);  // NPTS floats
    __shared__ float scx, scy, scz;
    __shared__ int snext;
    __shared__ float swv[16];
    __shared__ int swi[16];

    const int b = blockIdx.x;
    const float* P = pts + (size_t)b * NPTS * 3;
    const int t = threadIdx.x;

    float px[32], py[32], pz[32];
#pragma unroll
    for (int j = 0; j < 32; j++) {
        int idx = t + j * 512;
        px[j] = P[idx * 3 + 0];
        py[j] = P[idx * 3 + 1];
        pz[j] = P[idx * 3 + 2];
        sdist[idx] = 3.4e38f;
    }
    __syncthreads();

    int cur = 0;
    for (int g = 0; g < GRP; g++) {
        // broadcast coords of current farthest point
        if (t == (cur & 511)) {
            int j = cur >> 9;
            scx = px[j]; scy = py[j]; scz = pz[j];
        }
        __syncthreads();
        float cx = scx, cy = scy, cz = scz;

        if (t == 0) {
            size_t o = ((size_t)b * GRP + g) * 3;
            g_cent[o + 0] = cx; g_cent[o + 1] = cy; g_cent[o + 2] = cz;
            if (out_cent) {
                out_cent[o + 0] = cx; out_cent[o + 1] = cy; out_cent[o + 2] = cz;
            }
        }

        float bv = -1.0f;
        int bi = 0x7fffffff;
#pragma unroll
        for (int j = 0; j < 32; j++) {
            int idx = t + j * 512;
            float dx = px[j] - cx;
            float dy = py[j] - cy;
            float dz = pz[j] - cz;
            float d = dx * dx + dy * dy + dz * dz;
            float nd = fminf(sdist[idx], d);
            sdist[idx] = nd;
            if (nd > bv) { bv = nd; bi = idx; }  // idx ascending within thread
        }
        // warp argmax (tie -> lower index)
#pragma unroll
        for (int off = 16; off; off >>= 1) {
            float ov = __shfl_down_sync(0xffffffffu, bv, off);
            int oi = __shfl_down_sync(0xffffffffu, bi, off);
            if (ov > bv || (ov == bv && oi < bi)) { bv = ov; bi = oi; }
        }
        if ((t & 31) == 0) { swv[t >> 5] = bv; swi[t >> 5] = bi; }
        __syncthreads();
        if (t < 16) {
            bv = swv[t]; bi = swi[t];
#pragma unroll
            for (int off = 8; off; off >>= 1) {
                float ov = __shfl_down_sync(0x0000ffffu, bv, off);
                int oi = __shfl_down_sync(0x0000ffffu, bi, off);
                if (ov > bv || (ov == bv && oi < bi)) { bv = ov; bi = oi; }
            }
            if (t == 0) snext = bi;
        }
        __syncthreads();
        cur = snext;
    }
}

// ---------------------------------------------------------------------------
// Kernel 2: per-(b,g) exact top-64 smallest dist2 (radix select, matching
// lax.top_k stable tie semantics), then fused gelu-MLP first layer and mean
// over the 64 neighbors -> g_hbar[b*GRP+g][128].
// ---------------------------------------------------------------------------
__global__ __launch_bounds__(256) void group_kernel(const float* __restrict__ pts,
                                                    const float* __restrict__ w1,
                                                    const float* __restrict__ b1) {
    extern __shared__ unsigned char dyn_smem[];
    unsigned* s_keys = reinterpret_cast<unsigned*>(dyn_smem);  // NPTS keys

    __shared__ unsigned hist[256];
    __shared__ unsigned s_prefix;
    __shared__ int s_k;
    __shared__ int sel[KNN];
    __shared__ int eql[KNN];
    __shared__ int s_nless, s_neq;
    __shared__ float loc[KNN][3];
    __shared__ float hpart[256];

    const int g = blockIdx.x;
    const int b = blockIdx.y;
    const int t = threadIdx.x;

    const float* P = pts + (size_t)b * NPTS * 3;
    const float* C = g_cent + ((size_t)b * GRP + g) * 3;
    const float cx = C[0], cy = C[1], cz = C[2];
    const float c2 = cx * cx + cy * cy + cz * cz;

    // distances -> orderable uint keys in SMEM (reference formula)
    for (int i = t; i < NPTS; i += 256) {
        float x = P[i * 3 + 0], y = P[i * 3 + 1], z = P[i * 3 + 2];
        float p2 = x * x + y * y + z * z;
        float dot = cx * x + cy * y + cz * z;
        float f = (c2 + p2) - 2.0f * dot;
        unsigned u = __float_as_uint(f);
        u = (u & 0x80000000u) ? ~u : (u | 0x80000000u);
        s_keys[i] = u;
    }

    // 4-round MSB radix select: exact key of the 64th smallest
    unsigned prefix = 0;
    int k = KNN;
    for (int shift = 24; shift >= 0; shift -= 8) {
        hist[t & 255] = 0;  // 256 threads -> each zeros one bin
        __syncthreads();
        unsigned hmask = (shift == 24) ? 0u : (0xFFFFFFFFu << (shift + 8));
        for (int i = t; i < NPTS; i += 256) {
            unsigned key = s_keys[i];
            if ((key & hmask) == prefix)
                atomicAdd(&hist[(key >> shift) & 255u], 1u);
        }
        __syncthreads();
        if (t == 0) {
            unsigned cum = 0;
            for (int bin = 0; bin < 256; bin++) {
                unsigned c = hist[bin];
                if (cum + c >= (unsigned)k) {
                    s_k = k - (int)cum;
                    s_prefix = prefix | ((unsigned)bin << shift);
                    break;
                }
                cum += c;
            }
        }
        __syncthreads();
        prefix = s_prefix;
        k = s_k;
        __syncthreads();
    }
    const unsigned T = prefix;

    // gather: all keys < T, then fill with lowest-index ties == T
    if (t == 0) { s_nless = 0; s_neq = 0; }
    __syncthreads();
    for (int i = t; i < NPTS; i += 256) {
        unsigned key = s_keys[i];
        if (key < T) {
            int p = atomicAdd(&s_nless, 1);
            sel[p] = i;
        } else if (key == T) {
            int e = atomicAdd(&s_neq, 1);
            if (e < KNN) eql[e] = i;
        }
    }
    __syncthreads();
    if (t == 0) {
        int nless = s_nless;
        int need = KNN - nless;
        int m = (s_neq < KNN) ? s_neq : KNN;
        for (int a = 1; a < m; a++) {  // insertion sort (tiny)
            int v = eql[a];
            int c = a - 1;
            while (c >= 0 && eql[c] > v) { eql[c + 1] = eql[c]; c--; }
            eql[c + 1] = v;
        }
        for (int a = 0; a < need; a++) sel[nless + a] = eql[a];
    }
    __syncthreads();

    // local coords of selected neighbors
    if (t < KNN) {
        int idx = sel[t];
        loc[t][0] = P[idx * 3 + 0] - cx;
        loc[t][1] = P[idx * 3 + 1] - cy;
        loc[t][2] = P[idx * 3 + 2] - cz;
    }
    __syncthreads();

    // hbar[j] = mean_k gelu(loc_k . w1[:,j] + b1[j]); exact-erf gelu.
    // 256 threads: (j = t&127) x (half of k).
    const int j = t & 127;
    const float wx = w1[j], wy = w1[HID + j], wz = w1[2 * HID + j], bb = b1[j];
    float acc = 0.0f;
    const int k0 = (t >> 7) * 32;
#pragma unroll
    for (int kk = 0; kk < 32; kk++) {
        int kp = k0 + kk;
        float v = loc[kp][0] * wx + loc[kp][1] * wy + loc[kp][2] * wz + bb;
        float h = 0.5f * v * (1.0f + erff(v * 0.7071067811865476f));
        acc += h;
    }
    hpart[t] = acc;
    __syncthreads();
    if (t < HID)
        g_hbar[((size_t)b * GRP + g) * HID + t] =
            (hpart[t] + hpart[t + 128]) * (1.0f / (float)KNN);
}

// ---------------------------------------------------------------------------
// Kernel 3: tokens = hbar @ w2 + b2 (4096x384x128 GEMM), then LayerNorm.
// 16 rows per block, 384 threads (one output column each).
// ---------------------------------------------------------------------------
__global__ __launch_bounds__(384) void head_kernel(const float* __restrict__ w2,
                                                   const float* __restrict__ b2,
                                                   const float* __restrict__ gamma,
                                                   const float* __restrict__ beta,
                                                   float* __restrict__ out_tok) {
    __shared__ float sh[16 * HID];
    __shared__ float tok[16][DIM];

    const int row0 = blockIdx.x * 16;
    const int t = threadIdx.x;

    for (int i = t; i < 16 * HID; i += 384)
        sh[i] = g_hbar[(size_t)row0 * HID + i];
    __syncthreads();

    float acc[16];
#pragma unroll
    for (int r = 0; r < 16; r++) acc[r] = 0.0f;

    for (int jj = 0; jj < HID; jj++) {
        float w = w2[jj * DIM + t];
#pragma unroll
        for (int r = 0; r < 16; r++) acc[r] += sh[r * HID + jj] * w;
    }
    const float bd = b2[t];
#pragma unroll
    for (int r = 0; r < 16; r++) tok[r][t] = acc[r] + bd;
    __syncthreads();

    // LayerNorm per row: 12 warps cover 16 rows
    const int w = t >> 5, lane = t & 31;
    for (int r = w; r < 16; r += 12) {
        float s = 0.0f;
        for (int c = lane; c < DIM; c += 32) s += tok[r][c];
#pragma unroll
        for (int off = 16; off; off >>= 1) s += __shfl_xor_sync(0xffffffffu, s, off);
        float mu = s * (1.0f / DIM);
        float v = 0.0f;
        for (int c = lane; c < DIM; c += 32) {
            float d0 = tok[r][c] - mu;
            v += d0 * d0;
        }
#pragma unroll
        for (int off = 16; off; off >>= 1) v += __shfl_xor_sync(0xffffffffu, v, off);
        float rstd = rsqrtf(v * (1.0f / DIM) + 1e-5f);
        for (int c = lane; c < DIM; c += 32)
            out_tok[((size_t)row0 + r) * DIM + c] =
                (tok[r][c] - mu) * rstd * gamma[c] + beta[c];
    }
}

// ---------------------------------------------------------------------------
extern "C" void kernel_launch(void* const* d_in, const int* in_sizes, int n_in,
                              void* d_out, int out_size) {
    const float* pts   = (const float*)d_in[0];  // [32,16384,3]
    const float* w1    = (const float*)d_in[1];  // [3,128]
    const float* b1    = (const float*)d_in[2];  // [128]
    const float* w2    = (const float*)d_in[3];  // [128,384]
    const float* b2    = (const float*)d_in[4];  // [384]
    const float* gamma = (const float*)d_in[5];  // [384]
    const float* beta  = (const float*)d_in[6];  // [384]

    float* out = (float*)d_out;
    float* out_cent = nullptr;
    float* out_tok = out;
    // Expected layout: centroids [32,128,3] then tokens_ln [32,128,384]
    if (out_size == BATCH * GRP * (3 + DIM)) {
        out_cent = out;
        out_tok = out + BATCH * GRP * 3;
    }

    cudaFuncSetAttribute(fps_kernel, cudaFuncAttributeMaxDynamicSharedMemorySize,
                         NPTS * (int)sizeof(float));
    cudaFuncSetAttribute(group_kernel, cudaFuncAttributeMaxDynamicSharedMemorySize,
                         NPTS * (int)sizeof(unsigned));

    fps_kernel<<<BATCH, 512, NPTS * sizeof(float)>>>(pts, out_cent);
    group_kernel<<<dim3(GRP, BATCH), 256, NPTS * sizeof(unsigned)>>>(pts, w1, b1);
    head_kernel<<<(BATCH * GRP) / 16, 384>>>(w2, b2, gamma, beta, out_tok);
}

// round 6
// speedup vs baseline: 1.0022x; 1.0005x over previous
#include <cuda_runtime.h>

#define BATCH 32
#define NPTS  16384
#define GRP   128
#define KNN   64
#define HID   128
#define DIM   384

// Scratch (no allocations allowed)
__device__ float g_cent[BATCH * GRP * 3];
__device__ float g_hbar[BATCH * GRP * HID];

// ---------------------------------------------------------------------------
// Kernel 1: Farthest point sampling. One block per batch, 512 threads.
// Points live in registers (32/thread), running min-distance lives in SMEM
// (thread-private slots, strided layout -> conflict-free).
// Matches reference: idx[0]=0, emit current farthest BEFORE distance update,
// argmax picks lowest index on exact ties.
// ---------------------------------------------------------------------------
__global__ __launch_bounds__(512) void fps_kernel(const float* __restrict__ pts,
                                                  float* __restrict__ out_cent) {
    extern __shared__ unsigned char dyn_smem[];
    float* sdist = reinterpret_cast<float*>(dyn_smem);  // NPTS floats
    __shared__ float scx, scy, scz;
    __shared__ int snext;
    __shared__ float swv[16];
    __shared__ int swi[16];

    const int b = blockIdx.x;
    const float* P = pts + (size_t)b * NPTS * 3;
    const int t = threadIdx.x;

    float px[32], py[32], pz[32];
#pragma unroll
    for (int j = 0; j < 32; j++) {
        int idx = t + j * 512;
        px[j] = P[idx * 3 + 0];
        py[j] = P[idx * 3 + 1];
        pz[j] = P[idx * 3 + 2];
        sdist[idx] = 3.4e38f;
    }
    __syncthreads();

    int cur = 0;
    for (int g = 0; g < GRP; g++) {
        // broadcast coords of current farthest point
        if (t == (cur & 511)) {
            int j = cur >> 9;
            scx = px[j]; scy = py[j]; scz = pz[j];
        }
        __syncthreads();
        float cx = scx, cy = scy, cz = scz;

        if (t == 0) {
            size_t o = ((size_t)b * GRP + g) * 3;
            g_cent[o + 0] = cx; g_cent[o + 1] = cy; g_cent[o + 2] = cz;
            if (out_cent) {
                out_cent[o + 0] = cx; out_cent[o + 1] = cy; out_cent[o + 2] = cz;
            }
        }

        float bv = -1.0f;
        int bi = 0x7fffffff;
#pragma unroll
        for (int j = 0; j < 32; j++) {
            int idx = t + j * 512;
            float dx = px[j] - cx;
            float dy = py[j] - cy;
            float dz = pz[j] - cz;
            float d = dx * dx + dy * dy + dz * dz;
            float nd = fminf(sdist[idx], d);
            sdist[idx] = nd;
            if (nd > bv) { bv = nd; bi = idx; }  // idx ascending within thread
        }
        // warp argmax (tie -> lower index)
#pragma unroll
        for (int off = 16; off; off >>= 1) {
            float ov = __shfl_down_sync(0xffffffffu, bv, off);
            int oi = __shfl_down_sync(0xffffffffu, bi, off);
            if (ov > bv || (ov == bv && oi < bi)) { bv = ov; bi = oi; }
        }
        if ((t & 31) == 0) { swv[t >> 5] = bv; swi[t >> 5] = bi; }
        __syncthreads();
        if (t < 16) {
            bv = swv[t]; bi = swi[t];
#pragma unroll
            for (int off = 8; off; off >>= 1) {
                float ov = __shfl_down_sync(0x0000ffffu, bv, off);
                int oi = __shfl_down_sync(0x0000ffffu, bi, off);
                if (ov > bv || (ov == bv && oi < bi)) { bv = ov; bi = oi; }
            }
            if (t == 0) snext = bi;
        }
        __syncthreads();
        cur = snext;
    }
}

// ---------------------------------------------------------------------------
// Kernel 2: per-(b,g) exact top-64 smallest dist2 (radix select, matching
// lax.top_k stable tie semantics), then fused gelu-MLP first layer and mean
// over the 64 neighbors -> g_hbar[b*GRP+g][128].
// ---------------------------------------------------------------------------
__global__ __launch_bounds__(256) void group_kernel(const float* __restrict__ pts,
                                                    const float* __restrict__ w1,
                                                    const float* __restrict__ b1) {
    extern __shared__ unsigned char dyn_smem[];
    unsigned* s_keys = reinterpret_cast<unsigned*>(dyn_smem);  // NPTS keys

    __shared__ unsigned hist[256];
    __shared__ unsigned s_prefix;
    __shared__ int s_k;
    __shared__ int sel[KNN];
    __shared__ int eql[KNN];
    __shared__ int s_nless, s_neq;
    __shared__ float loc[KNN][3];
    __shared__ float hpart[256];

    const int g = blockIdx.x;
    const int b = blockIdx.y;
    const int t = threadIdx.x;

    const float* P = pts + (size_t)b * NPTS * 3;
    const float* C = g_cent + ((size_t)b * GRP + g) * 3;
    const float cx = C[0], cy = C[1], cz = C[2];
    const float c2 = cx * cx + cy * cy + cz * cz;

    // distances -> orderable uint keys in SMEM (reference formula)
    for (int i = t; i < NPTS; i += 256) {
        float x = P[i * 3 + 0], y = P[i * 3 + 1], z = P[i * 3 + 2];
        float p2 = x * x + y * y + z * z;
        float dot = cx * x + cy * y + cz * z;
        float f = (c2 + p2) - 2.0f * dot;
        unsigned u = __float_as_uint(f);
        u = (u & 0x80000000u) ? ~u : (u | 0x80000000u);
        s_keys[i] = u;
    }

    // 4-round MSB radix select: exact key of the 64th smallest
    unsigned prefix = 0;
    int k = KNN;
    for (int shift = 24; shift >= 0; shift -= 8) {
        hist[t & 255] = 0;  // 256 threads -> each zeros one bin
        __syncthreads();
        unsigned hmask = (shift == 24) ? 0u : (0xFFFFFFFFu << (shift + 8));
        for (int i = t; i < NPTS; i += 256) {
            unsigned key = s_keys[i];
            if ((key & hmask) == prefix)
                atomicAdd(&hist[(key >> shift) & 255u], 1u);
        }
        __syncthreads();
        if (t == 0) {
            unsigned cum = 0;
            for (int bin = 0; bin < 256; bin++) {
                unsigned c = hist[bin];
                if (cum + c >= (unsigned)k) {
                    s_k = k - (int)cum;
                    s_prefix = prefix | ((unsigned)bin << shift);
                    break;
                }
                cum += c;
            }
        }
        __syncthreads();
        prefix = s_prefix;
        k = s_k;
        __syncthreads();
    }
    const unsigned T = prefix;

    // gather: all keys < T, then fill with lowest-index ties == T
    if (t == 0) { s_nless = 0; s_neq = 0; }
    __syncthreads();
    for (int i = t; i < NPTS; i += 256) {
        unsigned key = s_keys[i];
        if (key < T) {
            int p = atomicAdd(&s_nless, 1);
            sel[p] = i;
        } else if (key == T) {
            int e = atomicAdd(&s_neq, 1);
            if (e < KNN) eql[e] = i;
        }
    }
    __syncthreads();
    if (t == 0) {
        int nless = s_nless;
        int need = KNN - nless;
        int m = (s_neq < KNN) ? s_neq : KNN;
        for (int a = 1; a < m; a++) {  // insertion sort (tiny)
            int v = eql[a];
            int c = a - 1;
            while (c >= 0 && eql[c] > v) { eql[c + 1] = eql[c]; c--; }
            eql[c + 1] = v;
        }
        for (int a = 0; a < need; a++) sel[nless + a] = eql[a];
    }
    __syncthreads();

    // local coords of selected neighbors
    if (t < KNN) {
        int idx = sel[t];
        loc[t][0] = P[idx * 3 + 0] - cx;
        loc[t][1] = P[idx * 3 + 1] - cy;
        loc[t][2] = P[idx * 3 + 2] - cz;
    }
    __syncthreads();

    // hbar[j] = mean_k gelu(loc_k . w1[:,j] + b1[j]); exact-erf gelu.
    // 256 threads: (j = t&127) x (half of k).
    const int j = t & 127;
    const float wx = w1[j], wy = w1[HID + j], wz = w1[2 * HID + j], bb = b1[j];
    float acc = 0.0f;
    const int k0 = (t >> 7) * 32;
#pragma unroll
    for (int kk = 0; kk < 32; kk++) {
        int kp = k0 + kk;
        float v = loc[kp][0] * wx + loc[kp][1] * wy + loc[kp][2] * wz + bb;
        float h = 0.5f * v * (1.0f + erff(v * 0.7071067811865476f));
        acc += h;
    }
    hpart[t] = acc;
    __syncthreads();
    if (t < HID)
        g_hbar[((size_t)b * GRP + g) * HID + t] =
            (hpart[t] + hpart[t + 128]) * (1.0f / (float)KNN);
}

// ---------------------------------------------------------------------------
// Kernel 3: tokens = hbar @ w2 + b2 (4096x384x128 GEMM), then LayerNorm.
// 16 rows per block, 384 threads (one output column each).
// ---------------------------------------------------------------------------
__global__ __launch_bounds__(384) void head_kernel(const float* __restrict__ w2,
                                                   const float* __restrict__ b2,
                                                   const float* __restrict__ gamma,
                                                   const float* __restrict__ beta,
                                                   float* __restrict__ out_tok) {
    __shared__ float sh[16 * HID];
    __shared__ float tok[16][DIM];

    const int row0 = blockIdx.x * 16;
    const int t = threadIdx.x;

    for (int i = t; i < 16 * HID; i += 384)
        sh[i] = g_hbar[(size_t)row0 * HID + i];
    __syncthreads();

    float acc[16];
#pragma unroll
    for (int r = 0; r < 16; r++) acc[r] = 0.0f;

    for (int jj = 0; jj < HID; jj++) {
        float w = w2[jj * DIM + t];
#pragma unroll
        for (int r = 0; r < 16; r++) acc[r] += sh[r * HID + jj] * w;
    }
    const float bd = b2[t];
#pragma unroll
    for (int r = 0; r < 16; r++) tok[r][t] = acc[r] + bd;
    __syncthreads();

    // LayerNorm per row: 12 warps cover 16 rows
    const int w = t >> 5, lane = t & 31;
    for (int r = w; r < 16; r += 12) {
        float s = 0.0f;
        for (int c = lane; c < DIM; c += 32) s += tok[r][c];
#pragma unroll
        for (int off = 16; off; off >>= 1) s += __shfl_xor_sync(0xffffffffu, s, off);
        float mu = s * (1.0f / DIM);
        float v = 0.0f;
        for (int c = lane; c < DIM; c += 32) {
            float d0 = tok[r][c] - mu;
            v += d0 * d0;
        }
#pragma unroll
        for (int off = 16; off; off >>= 1) v += __shfl_xor_sync(0xffffffffu, v, off);
        float rstd = rsqrtf(v * (1.0f / DIM) + 1e-5f);
        for (int c = lane; c < DIM; c += 32)
            out_tok[((size_t)row0 + r) * DIM + c] =
                (tok[r][c] - mu) * rstd * gamma[c] + beta[c];
    }
}

// ---------------------------------------------------------------------------
extern "C" void kernel_launch(void* const* d_in, const int* in_sizes, int n_in,
                              void* d_out, int out_size) {
    const float* pts   = (const float*)d_in[0];  // [32,16384,3]
    const float* w1    = (const float*)d_in[1];  // [3,128]
    const float* b1    = (const float*)d_in[2];  // [128]
    const float* w2    = (const float*)d_in[3];  // [128,384]
    const float* b2    = (const float*)d_in[4];  // [384]
    const float* gamma = (const float*)d_in[5];  // [384]
    const float* beta  = (const float*)d_in[6];  // [384]

    float* out = (float*)d_out;
    float* out_cent = nullptr;
    float* out_tok = out;
    // Expected layout: centroids [32,128,3] then tokens_ln [32,128,384]
    if (out_size == BATCH * GRP * (3 + DIM)) {
        out_cent = out;
        out_tok = out + BATCH * GRP * 3;
    }

    cudaFuncSetAttribute(fps_kernel, cudaFuncAttributeMaxDynamicSharedMemorySize,
                         NPTS * (int)sizeof(float));
    cudaFuncSetAttribute(group_kernel, cudaFuncAttributeMaxDynamicSharedMemorySize,
                         NPTS * (int)sizeof(unsigned));

    fps_kernel<<<BATCH, 512, NPTS * sizeof(float)>>>(pts, out_cent);
    group_kernel<<<dim3(GRP, BATCH), 256, NPTS * sizeof(unsigned)>>>(pts, w1, b1);
    head_kernel<<<(BATCH * GRP) / 16, 384>>>(w2, b2, gamma, beta, out_tok);
}